// round 11
// baseline (speedup 1.0000x reference)
#include <cuda_runtime.h>
#include <cuda_bf16.h>
#include <math.h>
#include <stdint.h>

// ---------------- problem constants ----------------
#define Bsz 1024
#define Dd 64
#define Mm 3
#define Cc 16384

#define TILE_C 128               // c per CTA
#define NTILES (Cc / TILE_C)     // 128 c-tiles
#define TILE_B 128               // b per chunk
#define NBT (Bsz / TILE_B)       // 8 b-chunks total
#define CPC 2                    // chunks per CTA
#define NBGRP (NBT / CPC)        // 4 b-groups
#define THREADS 256

#define FIN_BLOCKS 768           // finalize: 6144 items, 1 warp each

// SW128 swizzle: xor 16B-chunk index with row%8 (rows are 128B)
#define SWZ(o) ((o) ^ (((o) >> 3) & 0x70))

// ---------------- device scratch ----------------
__device__ __nv_bfloat16 g_featbf[2u * Bsz * Dd];        // 256 KB (branch-ordered)
__device__ float g_partial[2u * Mm * NTILES * Bsz];      // 3 MB
__device__ float g_bpart[FIN_BLOCKS];
__device__ int   g_sync;                                 // zero-init; reset by last block

// ---------------- PTX helpers (family-portable) ----------------
__device__ __forceinline__ uint32_t smem_u32(const void* p) {
    uint32_t a;
    asm("{ .reg .u64 t; cvta.to.shared.u64 t, %1; cvt.u32.u64 %0, t; }" : "=r"(a) : "l"(p));
    return a;
}
__device__ __forceinline__ void ldsm_x4(uint32_t* r, uint32_t addr) {
    asm volatile("ldmatrix.sync.aligned.m8n8.x4.shared.b16 {%0,%1,%2,%3}, [%4];"
                 : "=r"(r[0]), "=r"(r[1]), "=r"(r[2]), "=r"(r[3]) : "r"(addr));
}
__device__ __forceinline__ void ldsm_x2(uint32_t* r, uint32_t addr) {
    asm volatile("ldmatrix.sync.aligned.m8n8.x2.shared.b16 {%0,%1}, [%2];"
                 : "=r"(r[0]), "=r"(r[1]) : "r"(addr));
}
__device__ __forceinline__ void mma_bf16(float* d, const uint32_t* a, const uint32_t* b) {
    asm volatile("mma.sync.aligned.m16n8k16.row.col.f32.bf16.bf16.f32 "
                 "{%0,%1,%2,%3}, {%4,%5,%6,%7}, {%8,%9}, {%0,%1,%2,%3};"
                 : "+f"(d[0]), "+f"(d[1]), "+f"(d[2]), "+f"(d[3])
                 : "r"(a[0]), "r"(a[1]), "r"(a[2]), "r"(a[3]), "r"(b[0]), "r"(b[1]));
}
__device__ __forceinline__ uint32_t pbf2(float lo, float hi) {
    __nv_bfloat162 v = __floats2bfloat162_rn(lo, hi);
    return *(uint32_t*)&v;
}

// ---------------- kernel 1: feature fp32 -> bf16 (tiny; 32768 threads, 1 elem each) ----------------
__global__ __launch_bounds__(256)
void cvt_feat_kernel(const float* __restrict__ f0, const float* __restrict__ f1)
{
    const int FT4 = (Bsz * Dd) / 4;     // 16384 float4 per tensor
    const int i = blockIdx.x * 256 + threadIdx.x;   // 0 .. 2*FT4-1
    const int br = i >= FT4;
    const int j = i - br * FT4;
    float4 v = br ? ((const float4*)f0)[j] : ((const float4*)f1)[j]; // br0 <- features_I
    *(uint2*)&g_featbf[(size_t)i * 4] = make_uint2(pbf2(v.x, v.y), pbf2(v.z, v.w));
}

// ---------------- kernel 2: fused cvt(centroids) + mma GEMM + exp/row-sum ----------------
// CTA = (ctile, m, branch, bgrp): converts its 128x64 fp32 centroid tile to
// bf16 smem ONCE, then loops over CPC=2 feature chunks. 4 adjacent CTAs share
// the fp32 tile -> 1 DRAM read + 3 L2 hits, hidden under the HMMA stream.
__global__ __launch_bounds__(THREADS)
void pcl_mma_kernel(const float* __restrict__ cen0, const float* __restrict__ cen1,
                    const float* __restrict__ conc0, const float* __restrict__ conc1)
{
    __shared__ float sc[TILE_C];                     // log2e / conc[c]
    __shared__ __align__(16) char smA[TILE_B * 128]; // features  bf16 SW128 (16 KB)
    __shared__ __align__(16) char smB[TILE_C * 128]; // centroids bf16 SW128 (16 KB)
    __shared__ float ppart[2][TILE_B];               // per c-half row sums

    const int tid = threadIdx.x, wid = tid >> 5, lane = tid & 31;
    const int wrow = wid & 3;          // b-band (32 rows)
    const int wcol = wid >> 2;         // c-half (64 cols)
    const int ctile = blockIdx.x >> 2; // adjacent x share ctile -> L2 reuse
    const int bgrp  = blockIdx.x & (NBGRP - 1);
    const int m = blockIdx.y, branch = blockIdx.z;

    const float* cenf = (branch ? cen1 : cen0)
                        + ((size_t)m * Cc + (size_t)ctile * TILE_C) * Dd;
    const __nv_bfloat16* fbase = g_featbf + (size_t)branch * (Bsz * Dd);
    const float* conc = branch ? conc1 : conc0;

    if (tid < TILE_C)
        sc[tid] = 1.4426950408889634f / conc[m * Cc + ctile * TILE_C + tid];

    // ---- stage + convert centroid tile once: 128 rows x 64 fp32 -> bf16 SW128 ----
    {
        const float4* src = (const float4*)cenf;   // 16 float4 per row
        #pragma unroll
        for (int i = tid; i < 1024; i += THREADS) {  // uint4 (16B bf16 = 8 k) index
            int row = i >> 3, q = i & 7;
            float4 x0 = src[row * 16 + q * 2];
            float4 x1 = src[row * 16 + q * 2 + 1];
            *(uint4*)(smB + SWZ(row * 128 + q * 16)) =
                make_uint4(pbf2(x0.x, x0.y), pbf2(x0.z, x0.w),
                           pbf2(x1.x, x1.y), pbf2(x1.z, x1.w));
        }
    }

    const int a_row_in = ((lane >> 3) & 1) * 8 + (lane & 7);
    const int a_kofs   = (lane >> 4) * 8;
    const int bl       = lane & 15;
    const int b_row_in = bl & 7;
    const int b_kofs   = ((bl >> 3) & 1) * 8;

    float scr[8][2];
    const uint32_t smA32 = smem_u32(smA);
    const uint32_t smB32 = smem_u32(smB);

    for (int cc = 0; cc < CPC; ++cc) {
        const int bchunk = bgrp * CPC + cc;

        // stage bf16 feature chunk (L2-resident, 16 KB)
        {
            const uint4* fsrc = (const uint4*)(fbase + (size_t)bchunk * TILE_B * Dd);
            #pragma unroll
            for (int i = tid; i < 1024; i += THREADS) {
                int row = i >> 3, q = i & 7;
                *(uint4*)(smA + SWZ(row * 128 + q * 16)) = fsrc[i];
            }
        }
        __syncthreads();   // smA (+ smB/sc on first iter) ready

        if (cc == 0) {
            #pragma unroll
            for (int n = 0; n < 8; ++n) {
                int c0 = wcol * 64 + n * 8 + (lane & 3) * 2;
                scr[n][0] = sc[c0];
                scr[n][1] = sc[c0 + 1];
            }
        }

        float acc[2][8][4];
        #pragma unroll
        for (int mt = 0; mt < 2; ++mt)
            #pragma unroll
            for (int n = 0; n < 8; ++n)
                #pragma unroll
                for (int i = 0; i < 4; ++i) acc[mt][n][i] = 0.f;

        #pragma unroll
        for (int k4 = 0; k4 < 4; ++k4) {
            const int kb = k4 * 16;
            uint32_t afr[2][4];
            #pragma unroll
            for (int mt = 0; mt < 2; ++mt) {
                int row = wrow * 32 + mt * 16 + a_row_in;
                ldsm_x4(afr[mt], smA32 + SWZ(row * 128 + (kb + a_kofs) * 2));
            }
            #pragma unroll
            for (int n = 0; n < 8; ++n) {
                uint32_t bfr[2];
                int row = wcol * 64 + n * 8 + b_row_in;
                ldsm_x2(bfr, smB32 + SWZ(row * 128 + (kb + b_kofs) * 2));
                mma_bf16(acc[0][n], afr[0], bfr);
                mma_bf16(acc[1][n], afr[1], bfr);
            }
        }

        // ---- epilogue: exp + per-row sums, registers only ----
        float rs[2][2] = {{0.f, 0.f}, {0.f, 0.f}};
        #pragma unroll
        for (int mt = 0; mt < 2; ++mt)
            #pragma unroll
            for (int n = 0; n < 8; ++n)
                #pragma unroll
                for (int i = 0; i < 4; ++i) {
                    float x = acc[mt][n][i] * scr[n][i & 1];
                    float e;
                    asm("ex2.approx.ftz.f32 %0, %1;" : "=f"(e) : "f"(x));
                    rs[mt][i >> 1] += e;
                }

        #pragma unroll
        for (int mt = 0; mt < 2; ++mt)
            #pragma unroll
            for (int h = 0; h < 2; ++h) {
                rs[mt][h] += __shfl_xor_sync(0xFFFFFFFFu, rs[mt][h], 1);
                rs[mt][h] += __shfl_xor_sync(0xFFFFFFFFu, rs[mt][h], 2);
            }

        if ((lane & 3) == 0) {
            #pragma unroll
            for (int mt = 0; mt < 2; ++mt)
                #pragma unroll
                for (int h = 0; h < 2; ++h)
                    ppart[wcol][wrow * 32 + mt * 16 + h * 8 + (lane >> 2)] = rs[mt][h];
        }
        __syncthreads();   // ppart ready; also fences smA reads before restage

        if (tid < TILE_B) {
            g_partial[(((size_t)branch * Mm + m) * NTILES + ctile) * Bsz
                      + bchunk * TILE_B + tid] = ppart[0][tid] + ppart[1][tid];
        }
    }
}

// ---------------- kernel 3: finalize, warp-per-item (round-7 proven) ----------------
__global__ __launch_bounds__(256)
void pcl_final_kernel(const float* __restrict__ f0, const float* __restrict__ f1,
                      const float* __restrict__ cen0, const float* __restrict__ cen1,
                      const float* __restrict__ conc0, const float* __restrict__ conc1,
                      const int* __restrict__ lab0, const int* __restrict__ lab1,
                      const int* __restrict__ lbp, float* __restrict__ out)
{
    const int tid = threadIdx.x, lane = tid & 31, w = tid >> 5;
    const int item = blockIdx.x * 8 + w;        // 0..6143
    const int branch = item / (Mm * Bsz);
    const int r = item % (Mm * Bsz);
    const int m = r / Bsz;
    const int b = r % Bsz;

    const float* f    = branch ? f0   : f1;
    const float* cen  = branch ? cen1 : cen0;
    const float* conc = branch ? conc1 : conc0;
    const int*   lab  = branch ? lab1 : lab0;

    const int c = lab[m * Bsz + b];

    const float2 cv = ((const float2*)(cen + ((size_t)m * Cc + c) * Dd))[lane];
    const float2 fv = ((const float2*)(f + (size_t)b * Dd))[lane];
    float dot = cv.x * fv.x + cv.y * fv.y;

    const float* gp = &g_partial[(((size_t)branch * Mm + m) * NTILES) * Bsz + b];
    float se = gp[(size_t)(lane)       * Bsz] + gp[(size_t)(lane + 32) * Bsz]
             + gp[(size_t)(lane + 64)  * Bsz] + gp[(size_t)(lane + 96) * Bsz];

    #pragma unroll
    for (int off = 16; off > 0; off >>= 1) {
        dot += __shfl_xor_sync(0xFFFFFFFFu, dot, off);
        se  += __shfl_xor_sync(0xFFFFFFFFu, se, off);
    }

    __shared__ float wsum[8];
    if (lane == 0)
        wsum[w] = dot / conc[m * Cc + c] - logf(se);
    __syncthreads();

    __shared__ int isLast;
    if (tid == 0) {
        float s = 0.f;
        #pragma unroll
        for (int i = 0; i < 8; ++i) s += wsum[i];
        g_bpart[blockIdx.x] = s;
        __threadfence();
        isLast = (atomicAdd(&g_sync, 1) == FIN_BLOCKS - 1);
    }
    __syncthreads();

    if (isLast) {
        __threadfence();
        float s = g_bpart[tid] + g_bpart[tid + 256] + g_bpart[tid + 512];
        __shared__ float red[256];
        red[tid] = s;
        __syncthreads();
        for (int st = 128; st > 0; st >>= 1) {
            if (tid < st) red[tid] += red[tid + st];
            __syncthreads();
        }
        if (tid == 0) {
            out[0] = -((float)lbp[0] * red[0]) / (2.0f * (float)Bsz * (float)Mm);
            g_sync = 0;   // reset for next graph replay
        }
    }
}

// ---------------- launch ----------------
extern "C" void kernel_launch(void* const* d_in, const int* in_sizes, int n_in,
                              void* d_out, int out_size)
{
    const float* f0    = (const float*)d_in[0];
    const float* f1    = (const float*)d_in[1];
    const float* cen0  = (const float*)d_in[2];
    const float* cen1  = (const float*)d_in[3];
    const float* conc0 = (const float*)d_in[4];
    const float* conc1 = (const float*)d_in[5];
    const int*   lab0  = (const int*)d_in[6];
    const int*   lab1  = (const int*)d_in[7];
    const int*   lbp   = (const int*)d_in[8];
    float* out = (float*)d_out;

    cvt_feat_kernel<<<128, 256>>>(f0, f1);

    dim3 grid(NTILES * NBGRP, Mm, 2);   // 512 x 3 x 2 = 3072 CTAs, 2 chunks each
    pcl_mma_kernel<<<grid, THREADS>>>(cen0, cen1, conc0, conc1);

    pcl_final_kernel<<<FIN_BLOCKS, 256>>>(f0, f1, cen0, cen1, conc0, conc1,
                                          lab0, lab1, lbp, out);
}

// round 13
// speedup vs baseline: 1.5313x; 1.5313x over previous
#include <cuda_runtime.h>
#include <cuda_bf16.h>
#include <math.h>
#include <stdint.h>

// ---------------- problem constants ----------------
#define Bsz 1024
#define Dd 64
#define Mm 3
#define Cc 16384

#define TILE_C 128               // c per CTA
#define NTILES (Cc / TILE_C)     // 128 c-tiles
#define TILE_B 128               // b per CTA
#define NBT (Bsz / TILE_B)       // 8 b-chunks
#define THREADS 256

#define FIN_BLOCKS 768           // finalize: 6144 items, 1 warp each

// SW128 swizzle: xor 16B-chunk index with row%8 (rows are 128B)
#define SWZ(o) ((o) ^ (((o) >> 3) & 0x70))

// ---------------- device scratch ----------------
__device__ __nv_bfloat16 g_cenbf[2u * Mm * Cc * Dd];     // 12.6 MB
__device__ __nv_bfloat16 g_featbf[2u * Bsz * Dd];        // 256 KB (branch-ordered)
__device__ float g_partial[2u * Mm * NTILES * Bsz];      // 3 MB
__device__ float g_bpart[FIN_BLOCKS];
__device__ int   g_sync;                                 // zero-init; reset by last block

// ---------------- PTX helpers (family-portable) ----------------
__device__ __forceinline__ uint32_t smem_u32(const void* p) {
    uint32_t a;
    asm("{ .reg .u64 t; cvta.to.shared.u64 t, %1; cvt.u32.u64 %0, t; }" : "=r"(a) : "l"(p));
    return a;
}
__device__ __forceinline__ void ldsm_x4(uint32_t* r, uint32_t addr) {
    asm volatile("ldmatrix.sync.aligned.m8n8.x4.shared.b16 {%0,%1,%2,%3}, [%4];"
                 : "=r"(r[0]), "=r"(r[1]), "=r"(r[2]), "=r"(r[3]) : "r"(addr));
}
__device__ __forceinline__ void ldsm_x2(uint32_t* r, uint32_t addr) {
    asm volatile("ldmatrix.sync.aligned.m8n8.x2.shared.b16 {%0,%1}, [%2];"
                 : "=r"(r[0]), "=r"(r[1]) : "r"(addr));
}
__device__ __forceinline__ void mma_bf16(float* d, const uint32_t* a, const uint32_t* b) {
    asm volatile("mma.sync.aligned.m16n8k16.row.col.f32.bf16.bf16.f32 "
                 "{%0,%1,%2,%3}, {%4,%5,%6,%7}, {%8,%9}, {%0,%1,%2,%3};"
                 : "+f"(d[0]), "+f"(d[1]), "+f"(d[2]), "+f"(d[3])
                 : "r"(a[0]), "r"(a[1]), "r"(a[2]), "r"(a[3]), "r"(b[0]), "r"(b[1]));
}
__device__ __forceinline__ uint32_t pbf2(float lo, float hi) {
    __nv_bfloat162 v = __floats2bfloat162_rn(lo, hi);
    return *(uint32_t*)&v;
}

// ---------------- kernel 1: fp32 -> bf16 (round-7/10 proven) ----------------
__global__ __launch_bounds__(256)
void cvt_kernel(const float* __restrict__ f0, const float* __restrict__ f1,
                const float* __restrict__ cen0, const float* __restrict__ cen1)
{
    const int CEN4 = (Mm * Cc * Dd) / 4;
    const int FT4  = (Bsz * Dd) / 4;
    const int tid0 = blockIdx.x * blockDim.x + threadIdx.x;
    const int stride = gridDim.x * blockDim.x;

    // features first (main kernel's A operand): branch 0 <- features_I
    for (int i = tid0; i < 2 * FT4; i += stride) {
        int br = i >= FT4;
        int j  = i - br * FT4;
        float4 v = br ? ((const float4*)f0)[j] : ((const float4*)f1)[j];
        *(uint2*)&g_featbf[(size_t)i * 4] = make_uint2(pbf2(v.x, v.y), pbf2(v.z, v.w));
    }

    uint4* dst0 = (uint4*)g_cenbf;
    uint4* dst1 = (uint4*)(g_cenbf + (size_t)Mm * Cc * Dd);
    for (int i = tid0; i < CEN4 / 2; i += stride) {
        int s = i * 2;
        float4 a0 = ((const float4*)cen0)[s];
        float4 a1 = ((const float4*)cen0)[s + 1];
        float4 b0 = ((const float4*)cen1)[s];
        float4 b1 = ((const float4*)cen1)[s + 1];
        dst0[i] = make_uint4(pbf2(a0.x, a0.y), pbf2(a0.z, a0.w),
                             pbf2(a1.x, a1.y), pbf2(a1.z, a1.w));
        dst1[i] = make_uint4(pbf2(b0.x, b0.y), pbf2(b0.z, b0.w),
                             pbf2(b1.x, b1.y), pbf2(b1.z, b1.w));
    }
#if __CUDA_ARCH__ >= 900
    cudaTriggerProgrammaticLaunchCompletion();
#endif
}

// ---------------- kernel 2: mma.sync bf16 GEMM + fused exp/row-sum ----------------
// PDL secondary of cvt: loads conc (independent) before grid-dep sync.
__global__ __launch_bounds__(THREADS)
void pcl_mma_kernel(const float* __restrict__ conc0, const float* __restrict__ conc1)
{
    __shared__ float sc[TILE_C];                     // log2e / conc[c]
    __shared__ __align__(16) char smA[TILE_B * 128]; // features  128 x 128B SW128
    __shared__ __align__(16) char smB[TILE_C * 128]; // centroids 128 x 128B SW128
    __shared__ float ppart[2][TILE_B];               // per c-half row sums

    const int tid = threadIdx.x, wid = tid >> 5, lane = tid & 31;
    const int wrow = wid & 3;          // b-band (32 rows)
    const int wcol = wid >> 2;         // c-half (64 cols)
    const int bchunk = blockIdx.x & (NBT - 1);
    const int ctile  = blockIdx.x >> 3;
    const int m = blockIdx.y, branch = blockIdx.z;

    const float* conc = branch ? conc1 : conc0;
    if (tid < TILE_C)
        sc[tid] = 1.4426950408889634f / conc[m * Cc + ctile * TILE_C + tid];

#if __CUDA_ARCH__ >= 900
    cudaGridDependencySynchronize();   // wait for cvt's bf16 outputs
#endif

    const __nv_bfloat16* cenb = g_cenbf + (size_t)branch * (Mm * Cc * Dd)
                                + ((size_t)m * Cc + (size_t)ctile * TILE_C) * Dd;
    const __nv_bfloat16* fb   = g_featbf + (size_t)branch * (Bsz * Dd)
                                + (size_t)bchunk * TILE_B * Dd;

    {
        const uint4* fsrc = (const uint4*)fb;
        const uint4* csrc = (const uint4*)cenb;
        #pragma unroll
        for (int i = tid; i < 1024; i += THREADS) {
            int row = i >> 3, q = i & 7;
            *(uint4*)(smA + SWZ(row * 128 + q * 16)) = fsrc[i];
            *(uint4*)(smB + SWZ(row * 128 + q * 16)) = csrc[i];
        }
    }
    __syncthreads();

    const uint32_t smA32 = smem_u32(smA);
    const uint32_t smB32 = smem_u32(smB);

    const int a_row_in = ((lane >> 3) & 1) * 8 + (lane & 7);
    const int a_kofs   = (lane >> 4) * 8;
    const int bl       = lane & 15;
    const int b_row_in = bl & 7;
    const int b_kofs   = ((bl >> 3) & 1) * 8;

    float acc[2][8][4];
    #pragma unroll
    for (int mt = 0; mt < 2; ++mt)
        #pragma unroll
        for (int n = 0; n < 8; ++n)
            #pragma unroll
            for (int i = 0; i < 4; ++i) acc[mt][n][i] = 0.f;

    #pragma unroll
    for (int k4 = 0; k4 < 4; ++k4) {
        const int kb = k4 * 16;
        uint32_t afr[2][4];
        #pragma unroll
        for (int mt = 0; mt < 2; ++mt) {
            int row = wrow * 32 + mt * 16 + a_row_in;
            ldsm_x4(afr[mt], smA32 + SWZ(row * 128 + (kb + a_kofs) * 2));
        }
        #pragma unroll
        for (int n = 0; n < 8; ++n) {
            uint32_t bfr[2];
            int row = wcol * 64 + n * 8 + b_row_in;
            ldsm_x2(bfr, smB32 + SWZ(row * 128 + (kb + b_kofs) * 2));
            mma_bf16(acc[0][n], afr[0], bfr);
            mma_bf16(acc[1][n], afr[1], bfr);
        }
    }

    float scr[8][2];
    #pragma unroll
    for (int n = 0; n < 8; ++n) {
        int c0 = wcol * 64 + n * 8 + (lane & 3) * 2;
        scr[n][0] = sc[c0];
        scr[n][1] = sc[c0 + 1];
    }

    float rs[2][2] = {{0.f, 0.f}, {0.f, 0.f}};
    #pragma unroll
    for (int mt = 0; mt < 2; ++mt)
        #pragma unroll
        for (int n = 0; n < 8; ++n)
            #pragma unroll
            for (int i = 0; i < 4; ++i) {
                float x = acc[mt][n][i] * scr[n][i & 1];
                float e;
                asm("ex2.approx.ftz.f32 %0, %1;" : "=f"(e) : "f"(x));
                rs[mt][i >> 1] += e;
            }

    #pragma unroll
    for (int mt = 0; mt < 2; ++mt)
        #pragma unroll
        for (int h = 0; h < 2; ++h) {
            rs[mt][h] += __shfl_xor_sync(0xFFFFFFFFu, rs[mt][h], 1);
            rs[mt][h] += __shfl_xor_sync(0xFFFFFFFFu, rs[mt][h], 2);
        }

    if ((lane & 3) == 0) {
        #pragma unroll
        for (int mt = 0; mt < 2; ++mt)
            #pragma unroll
            for (int h = 0; h < 2; ++h)
                ppart[wcol][wrow * 32 + mt * 16 + h * 8 + (lane >> 2)] = rs[mt][h];
    }
    __syncthreads();

    if (tid < TILE_B) {
        g_partial[(((size_t)branch * Mm + m) * NTILES + ctile) * Bsz + bchunk * TILE_B + tid] =
            ppart[0][tid] + ppart[1][tid];
    }
#if __CUDA_ARCH__ >= 900
    cudaTriggerProgrammaticLaunchCompletion();
#endif
}

// ---------------- kernel 3: finalize, warp-per-item + PDL prefetch ----------------
// Independent phase (labels, positive dot, conc, lb) fully reduced BEFORE the
// grid-dep sync -> overlaps the main kernel's drain; g_partial reads after.
__global__ __launch_bounds__(256)
void pcl_final_kernel(const float* __restrict__ f0, const float* __restrict__ f1,
                      const float* __restrict__ cen0, const float* __restrict__ cen1,
                      const float* __restrict__ conc0, const float* __restrict__ conc1,
                      const int* __restrict__ lab0, const int* __restrict__ lab1,
                      const int* __restrict__ lbp, float* __restrict__ out)
{
    const int tid = threadIdx.x, lane = tid & 31, w = tid >> 5;
    const int item = blockIdx.x * 8 + w;        // 0..6143
    const int branch = item / (Mm * Bsz);
    const int r = item % (Mm * Bsz);
    const int m = r / Bsz;
    const int b = r % Bsz;

    const float* f    = branch ? f0   : f1;
    const float* cen  = branch ? cen1 : cen0;
    const float* conc = branch ? conc1 : conc0;
    const int*   lab  = branch ? lab1 : lab0;

    // ---- independent-phase loads, front-batched ----
    const int c = lab[m * Bsz + b];
    const int lbv = lbp[0];
    const float2 cv = ((const float2*)(cen + ((size_t)m * Cc + c) * Dd))[lane];
    const float2 fv = ((const float2*)(f + (size_t)b * Dd))[lane];
    const float invc = 1.0f / conc[m * Cc + c];

    float dot = cv.x * fv.x + cv.y * fv.y;
    #pragma unroll
    for (int off = 16; off > 0; off >>= 1)
        dot += __shfl_xor_sync(0xFFFFFFFFu, dot, off);

#if __CUDA_ARCH__ >= 900
    cudaGridDependencySynchronize();   // wait for main's g_partial
#endif

    const float* gp = &g_partial[(((size_t)branch * Mm + m) * NTILES) * Bsz + b];
    float se = gp[(size_t)(lane)       * Bsz] + gp[(size_t)(lane + 32) * Bsz]
             + gp[(size_t)(lane + 64)  * Bsz] + gp[(size_t)(lane + 96) * Bsz];
    #pragma unroll
    for (int off = 16; off > 0; off >>= 1)
        se += __shfl_xor_sync(0xFFFFFFFFu, se, off);

    __shared__ float wsum[8];
    if (lane == 0)
        wsum[w] = dot * invc - logf(se);
    __syncthreads();

    __shared__ int isLast;
    if (tid == 0) {
        float s = 0.f;
        #pragma unroll
        for (int i = 0; i < 8; ++i) s += wsum[i];
        g_bpart[blockIdx.x] = s;
        __threadfence();
        isLast = (atomicAdd(&g_sync, 1) == FIN_BLOCKS - 1);
    }
    __syncthreads();

    if (isLast) {
        __threadfence();
        float s = g_bpart[tid] + g_bpart[tid + 256] + g_bpart[tid + 512];
        __shared__ float red[256];
        red[tid] = s;
        __syncthreads();
        for (int st = 128; st > 0; st >>= 1) {
            if (tid < st) red[tid] += red[tid + st];
            __syncthreads();
        }
        if (tid == 0) {
            out[0] = -((float)lbv * red[0]) / (2.0f * (float)Bsz * (float)Mm);
            g_sync = 0;   // reset for next graph replay
        }
    }
}

// ---------------- launch: PDL-chained ----------------
extern "C" void kernel_launch(void* const* d_in, const int* in_sizes, int n_in,
                              void* d_out, int out_size)
{
    const float* f0    = (const float*)d_in[0];
    const float* f1    = (const float*)d_in[1];
    const float* cen0  = (const float*)d_in[2];
    const float* cen1  = (const float*)d_in[3];
    const float* conc0 = (const float*)d_in[4];
    const float* conc1 = (const float*)d_in[5];
    const int*   lab0  = (const int*)d_in[6];
    const int*   lab1  = (const int*)d_in[7];
    const int*   lbp   = (const int*)d_in[8];
    float* out = (float*)d_out;

    cvt_kernel<<<1184, 256>>>(f0, f1, cen0, cen1);

    cudaLaunchAttribute attr[1];
    attr[0].id = cudaLaunchAttributeProgrammaticStreamSerialization;
    attr[0].val.programmaticStreamSerializationAllowed = 1;

    {   // main: PDL secondary of cvt
        cudaLaunchConfig_t cfg = {};
        cfg.gridDim  = dim3(NBT * NTILES, Mm, 2);   // 1024 x 3 x 2
        cfg.blockDim = dim3(THREADS, 1, 1);
        cfg.stream = 0;
        cfg.attrs = attr;
        cfg.numAttrs = 1;
        cudaLaunchKernelEx(&cfg, pcl_mma_kernel, conc0, conc1);
    }
    {   // final: PDL secondary of main
        cudaLaunchConfig_t cfg = {};
        cfg.gridDim  = dim3(FIN_BLOCKS, 1, 1);
        cfg.blockDim = dim3(256, 1, 1);
        cfg.stream = 0;
        cfg.attrs = attr;
        cfg.numAttrs = 1;
        cudaLaunchKernelEx(&cfg, pcl_final_kernel,
                           f0, f1, cen0, cen1, conc0, conc1, lab0, lab1, lbp, out);
    }
}